// round 15
// baseline (speedup 1.0000x reference)
#include <cuda_runtime.h>
#include <cuda_fp16.h>
#include <math.h>

#define NCHK 256
#define BSZ 32
#define NROWS (BSZ * NCHK * 16)   // 131072 rows of the flattened GEMM
#define NTILES (NROWS / 64)

// ---------------- scratch (static device globals; no allocation) -------------
__device__ int   g_is64;
__device__ float g_watch[NROWS * 16];  // [row][16]
__device__ float g_A[NROWS * 64];      // [(b*16+r)*NCHK + t][64]
__device__ float g_sus[NROWS * 64];    // [row][64]
__device__ uint2 g_Bfrag2[5 * 64 * 32]; // Wd fp16 fragments

// ---------------- packed f32x2 / misc helpers ---------------------------------
__device__ __forceinline__ unsigned long long pk2(float lo, float hi) {
    unsigned long long r;
    asm("mov.b64 %0, {%1,%2};" : "=l"(r) : "f"(lo), "f"(hi));
    return r;
}
__device__ __forceinline__ void upk2(unsigned long long v, float& lo, float& hi) {
    asm("mov.b64 {%0,%1}, %2;" : "=f"(lo), "=f"(hi) : "l"(v));
}
__device__ __forceinline__ unsigned long long fma2(unsigned long long a,
                                                   unsigned long long b,
                                                   unsigned long long c) {
    unsigned long long d;
    asm("fma.rn.f32x2 %0, %1, %2, %3;" : "=l"(d) : "l"(a), "l"(b), "l"(c));
    return d;
}

__device__ __forceinline__ unsigned pack_h2(float a, float b) {
    __half ha = __float2half_rn(a), hb = __float2half_rn(b);
    return (unsigned)__half_as_ushort(ha) | ((unsigned)__half_as_ushort(hb) << 16);
}

__device__ __forceinline__ void mma16816h(float* d,
                                          unsigned a0, unsigned a1, unsigned a2, unsigned a3,
                                          unsigned b0, unsigned b1) {
    asm volatile(
        "mma.sync.aligned.m16n8k16.row.col.f32.f16.f16.f32 "
        "{%0,%1,%2,%3}, {%4,%5,%6,%7}, {%8,%9}, {%0,%1,%2,%3};"
        : "+f"(d[0]), "+f"(d[1]), "+f"(d[2]), "+f"(d[3])
        : "r"(a0), "r"(a1), "r"(a2), "r"(a3), "r"(b0), "r"(b1));
}

// ---------------- kernel 0: detect int32 vs int64 token ids ------------------
__global__ void k_detect(const unsigned int* __restrict__ x) {
    unsigned int v = x[threadIdx.x * 2 + 1];
    unsigned int any = __ballot_sync(0xffffffffu, v != 0u);
    if (threadIdx.x == 0) g_is64 = (any == 0u) ? 1 : 0;
}

// ---------------- kernel: pre-split Wd into fragment-ordered fp16 ------------
__global__ void k_prepB(const float* __restrict__ Wd) {
    int w = blockIdx.x * blockDim.x + threadIdx.x;   // 0..10239
    if (w >= 5 * 64 * 32) return;
    int lane = w & 31;
    int ntg  = (w >> 5) & 63;
    int ks   = w >> 11;
    int g = lane >> 2, tig = lane & 3;
    int n  = ntg * 8 + g;
    int k0 = ks * 16 + tig * 2;
    float w00 = Wd[k0 * 512 + n],       w01 = Wd[(k0 + 1) * 512 + n];
    float w10 = Wd[(k0 + 8) * 512 + n], w11 = Wd[(k0 + 9) * 512 + n];
    g_Bfrag2[w] = make_uint2(pack_h2(w00, w01), pack_h2(w10, w11));
}

// ---------------- Phase A: attention + LN + A = watch@Ws_top + bs ------------
__global__ __launch_bounds__(256) void k_phaseA(
    const void* __restrict__ xraw, const float* __restrict__ emb,
    const float* __restrict__ Wq, const float* __restrict__ bq,
    const float* __restrict__ Wk, const float* __restrict__ bk,
    const float* __restrict__ Wv, const float* __restrict__ bv,
    const float* __restrict__ glim, const float* __restrict__ blim,
    const float* __restrict__ Ws, const float* __restrict__ bs)
{
    int bt = blockIdx.x;
    int tid = threadIdx.x;
    int i = tid >> 4, j = tid & 15;

    __shared__ float rd[16][17], qs[16][17], ks[16][17], vs[16][17];
    __shared__ float ps[16][17], wls[16][17];
    __shared__ float wq_s[256], wk_s[256], wv_s[256];
    __shared__ float ws_s[16 * 64];   // Ws rows 0..15 (the watch part)

    wq_s[tid] = Wq[tid];
    wk_s[tid] = Wk[tid];
    wv_s[tid] = Wv[tid];
    #pragma unroll
    for (int k = 0; k < 4; k++) ws_s[tid + k * 256] = Ws[tid + k * 256];

    long long id;
    int xbase = bt * 16 + i;
    if (g_is64) id = ((const long long*)xraw)[xbase];
    else        id = (long long)((const int*)xraw)[xbase];
    rd[i][j] = emb[(int)id * 16 + j];
    __syncthreads();

    float aq = bq[j], ak = bk[j], av = bv[j];
    #pragma unroll
    for (int d = 0; d < 16; d++) {
        float r = rd[i][d];
        aq = fmaf(r, wq_s[d * 16 + j], aq);
        ak = fmaf(r, wk_s[d * 16 + j], ak);
        av = fmaf(r, wv_s[d * 16 + j], av);
    }
    qs[i][j] = aq; ks[i][j] = ak; vs[i][j] = av;
    __syncthreads();

    float sc = 0.f;
    #pragma unroll
    for (int d = 0; d < 16; d++) sc = fmaf(qs[i][d], ks[j][d], sc);
    sc *= 0.25f;

    float mx = sc;
    #pragma unroll
    for (int o = 8; o; o >>= 1) mx = fmaxf(mx, __shfl_xor_sync(0xffffffffu, mx, o));
    float e = __expf(sc - mx);
    float sm = e;
    #pragma unroll
    for (int o = 8; o; o >>= 1) sm += __shfl_xor_sync(0xffffffffu, sm, o);
    float p = e / sm;
    ps[i][j] = p;
    __syncthreads();

    float w = 0.f;
    #pragma unroll
    for (int d = 0; d < 16; d++) w = fmaf(ps[i][d], vs[d][j], w);

    float s1 = w, s2 = w * w;
    #pragma unroll
    for (int o = 8; o; o >>= 1) {
        s1 += __shfl_xor_sync(0xffffffffu, s1, o);
        s2 += __shfl_xor_sync(0xffffffffu, s2, o);
    }
    float mean = s1 * 0.0625f;
    float var = fmaxf(s2 * 0.0625f - mean * mean, 0.0f);
    float wl = (w - mean) * rsqrtf(var + 1e-5f) * glim[j] + blim[j];

    g_watch[(bt * 16 + i) * 16 + j] = wl;
    wls[i][j] = wl;
    __syncthreads();

    int b = bt >> 8, t = bt & 255;
    int abase = ((b * 16 + i) * NCHK + t) * 64;
    #pragma unroll
    for (int cc = 0; cc < 4; cc++) {
        int c = j + cc * 16;
        float a = bs[c];
        #pragma unroll
        for (int d = 0; d < 16; d++) a = fmaf(wls[i][d], ws_s[d * 64 + c], a);
        g_A[abase + c] = a;
    }
}

// ---------------- Phase B: TWO chains per warp (ILP across chains) -----------
// The ~600-cyc step chain is structural; instead of shortening it, run two
// independent chains per warp. Both share the SAME weight registers, so the
// marginal cost is ~30 regs of state; the warp's idle issue slots (66%)
// absorb the second chain's instructions.
__global__ __launch_bounds__(128) void k_phaseB(
    const float* __restrict__ Ws,
    const float* __restrict__ gdb, const float* __restrict__ bdb)
{
    int wid = threadIdx.x >> 5;
    int lane = threadIdx.x & 31;
    int brA = blockIdx.x * 8 + wid * 2;   // chains brA, brA+1
    int brB = brA + 1;
    int j0 = lane, j1 = lane + 32;

    __shared__ __align__(16) float2 gsh[4][2][2][32];  // [warp][chain][pbuf][lane]
    __shared__ float gdsh[64], bdsh[64];

    if (threadIdx.x < 64) {
        gdsh[threadIdx.x] = gdb[threadIdx.x];
        bdsh[threadIdx.x] = bdb[threadIdx.x];
    }
    __syncthreads();

    // shared-across-chains per-column weights
    unsigned long long w2a[32], w2b[32];
    float q0 = 0.f, q1 = 0.f, c0 = 0.f, c1 = 0.f;
    #pragma unroll
    for (int i = 0; i < 32; i++) {
        float wa0 = Ws[(16 + i) * 64 + j0];
        float wb0 = Ws[(16 + i + 32) * 64 + j0];
        float wa1 = Ws[(16 + i) * 64 + j1];
        float wb1 = Ws[(16 + i + 32) * 64 + j1];
        float gi = gdsh[i], gi32 = gdsh[i + 32];
        float va0 = wa0 * gi, vb0 = wb0 * gi32;
        float va1 = wa1 * gi, vb1 = wb1 * gi32;
        w2a[i] = pk2(va0, vb0);
        w2b[i] = pk2(va1, vb1);
        q0 += va0 + vb0; q1 += va1 + vb1;
        c0 = fmaf(bdsh[i], wa0, c0); c0 = fmaf(bdsh[i + 32], wb0, c0);
        c1 = fmaf(bdsh[i], wa1, c1); c1 = fmaf(bdsh[i + 32], wb1, c1);
    }
    float gd0 = gdsh[j0], gd1 = gdsh[j1];
    float bd0 = bdsh[j0], bd1 = bdsh[j1];

    const float* ArowA = g_A + (size_t)brA * (NCHK * 64);
    const float* ArowB = g_A + (size_t)brB * (NCHK * 64);
    float* suspA = g_sus + (size_t)(brA >> 4) * (NCHK * 16 * 64) + (size_t)(brA & 15) * 64;
    float* suspB = g_sus + (size_t)(brB >> 4) * (NCHK * 16 * 64) + (size_t)(brB & 15) * 64;

    float paA[4], pbA[4], paB[4], pbB[4];
    #pragma unroll
    for (int d = 0; d < 4; d++) {
        paA[d] = ArowA[d * 64 + j0];
        pbA[d] = ArowA[d * 64 + j1];
        paB[d] = ArowB[d * 64 + j0];
        pbB[d] = ArowB[d * 64 + j1];
    }

    float gA0 = 0.f, gA1 = 0.f, meanA = 0.f, invA = 0.f, pA0 = 0.f, pA1 = 0.f;
    float gB0 = 0.f, gB1 = 0.f, meanB = 0.f, invB = 0.f, pB0 = 0.f, pB1 = 0.f;

    for (int tt = 0; tt < NCHK; tt += 4) {
        #pragma unroll
        for (int d = 0; d < 4; d++) {
            int t = tt + d;
            float sA0 = (t == 0) ? 0.f : (gA0 - meanA) * invA * gd0 + bd0;
            float sA1 = (t == 0) ? 0.f : (gA1 - meanA) * invA * gd1 + bd1;
            float sB0 = (t == 0) ? 0.f : (gB0 - meanB) * invB * gd0 + bd0;
            float sB1 = (t == 0) ? 0.f : (gB1 - meanB) * invB * gd1 + bd1;
            suspA[(size_t)t * 1024 + j0] = sA0;
            suspA[(size_t)t * 1024 + j1] = sA1;
            suspB[(size_t)t * 1024 + j0] = sB0;
            suspB[(size_t)t * 1024 + j1] = sB1;
            if (t == NCHK - 1) break;

            float nimA = -(invA * meanA);
            float nimB = -(invB * meanB);
            float hA0 = (t == 0) ? paA[0] : fmaf(invA, pA0, fmaf(nimA, q0, paA[d] + c0));
            float hA1 = (t == 0) ? pbA[0] : fmaf(invA, pA1, fmaf(nimA, q1, pbA[d] + c1));
            float hB0 = (t == 0) ? paB[0] : fmaf(invB, pB0, fmaf(nimB, q0, paB[d] + c0));
            float hB1 = (t == 0) ? pbB[0] : fmaf(invB, pB1, fmaf(nimB, q1, pbB[d] + c1));

            if (t + 4 < NCHK) {
                paA[d] = ArowA[(t + 4) * 64 + j0];
                pbA[d] = ArowA[(t + 4) * 64 + j1];
                paB[d] = ArowB[(t + 4) * 64 + j0];
                pbB[d] = ArowB[(t + 4) * 64 + j1];
            }

            gA0 = 0.5f * hA0 * (1.0f + erff(hA0 * 0.70710678118654752f));
            gA1 = 0.5f * hA1 * (1.0f + erff(hA1 * 0.70710678118654752f));
            gB0 = 0.5f * hB0 * (1.0f + erff(hB0 * 0.70710678118654752f));
            gB1 = 0.5f * hB1 * (1.0f + erff(hB1 * 0.70710678118654752f));

            int pbuf = t & 1;
            gsh[wid][0][pbuf][lane] = make_float2(gA0, gA1);
            gsh[wid][1][pbuf][lane] = make_float2(gB0, gB1);

            // interleaved butterfly reduces for both chains
            float r1A = gA0 + gA1, r2A = fmaf(gA0, gA0, gA1 * gA1);
            float r1B = gB0 + gB1, r2B = fmaf(gB0, gB0, gB1 * gB1);
            #pragma unroll
            for (int o = 16; o; o >>= 1) {
                r1A += __shfl_xor_sync(0xffffffffu, r1A, o);
                r2A += __shfl_xor_sync(0xffffffffu, r2A, o);
                r1B += __shfl_xor_sync(0xffffffffu, r1B, o);
                r2B += __shfl_xor_sync(0xffffffffu, r2B, o);
            }
            __syncwarp();

            meanA = r1A * (1.0f / 64.0f);
            invA = rsqrtf(fmaxf(r2A * (1.0f / 64.0f) - meanA * meanA, 0.0f) + 1e-5f);
            meanB = r1B * (1.0f / 64.0f);
            invB = rsqrtf(fmaxf(r2B * (1.0f / 64.0f) - meanB * meanB, 0.0f) + 1e-5f);

            // matvec chain A
            {
                const unsigned long long* g2 = (const unsigned long long*)gsh[wid][0][pbuf];
                unsigned long long x0 = 0ull, x1 = 0ull, y0 = 0ull, y1 = 0ull;
                #pragma unroll
                for (int i = 0; i < 32; i += 2) {
                    unsigned long long ga = g2[i], gb = g2[i + 1];
                    x0 = fma2(ga, w2a[i],     x0);  y0 = fma2(ga, w2b[i],     y0);
                    x1 = fma2(gb, w2a[i + 1], x1);  y1 = fma2(gb, w2b[i + 1], y1);
                }
                float la, ha, lb, hb;
                upk2(x0, la, ha); upk2(x1, lb, hb);
                pA0 = (la + ha) + (lb + hb);
                upk2(y0, la, ha); upk2(y1, lb, hb);
                pA1 = (la + ha) + (lb + hb);
            }
            // matvec chain B
            {
                const unsigned long long* g2 = (const unsigned long long*)gsh[wid][1][pbuf];
                unsigned long long x0 = 0ull, x1 = 0ull, y0 = 0ull, y1 = 0ull;
                #pragma unroll
                for (int i = 0; i < 32; i += 2) {
                    unsigned long long ga = g2[i], gb = g2[i + 1];
                    x0 = fma2(ga, w2a[i],     x0);  y0 = fma2(ga, w2b[i],     y0);
                    x1 = fma2(gb, w2a[i + 1], x1);  y1 = fma2(gb, w2b[i + 1], y1);
                }
                float la, ha, lb, hb;
                upk2(x0, la, ha); upk2(x1, lb, hb);
                pB0 = (la + ha) + (lb + hb);
                upk2(y0, la, ha); upk2(y1, lb, hb);
                pB1 = (la + ha) + (lb + hb);
            }
        }
    }
}

// ---------------- Phase C: fp16 SINGLE-pass tensor GEMM + row LN -------------
#define C_SMEM_B    (5 * 64 * 32 * 8)    // 81920 (uint2 fragments)
#define C_SMEM_A    (5 * 4 * 32 * 16)    // 10240 (one fp16 plane)
#define C_SMEM_RED  4096
#define C_SMEM_VEC  (3 * 2048)
#define C_SMEM_BYTES (C_SMEM_B + C_SMEM_A + C_SMEM_RED + C_SMEM_VEC)

__global__ __launch_bounds__(512, 1) void k_phaseC(
    const float* __restrict__ bd, const float* __restrict__ gch,
    const float* __restrict__ bch, float* __restrict__ out)
{
    extern __shared__ char sm[];
    uint2*  sB   = (uint2*)sm;                                   // [5][64][32]
    unsigned* sAh = (unsigned*)(sm + C_SMEM_B);                  // [5][4][32][4]
    float2* sRed = (float2*)(sm + C_SMEM_B + C_SMEM_A);          // [64][8]
    float*  sG   = (float*)(sm + C_SMEM_B + C_SMEM_A + C_SMEM_RED);
    float*  sBc  = sG + 512;
    float*  sBd  = sBc + 512;

    int tid = threadIdx.x;
    int lane = tid & 31, warp = tid >> 5;
    int mw = warp & 1, nw = warp >> 1;        // 2 m-warps x 8 n-warps
    int g = lane >> 2, tig = lane & 3;

    for (int i = tid; i < 5 * 64 * 32; i += 512) sB[i] = g_Bfrag2[i];
    if (tid < 512) { sG[tid] = gch[tid]; sBc[tid] = bch[tid]; sBd[tid] = bd[tid]; }
    __syncthreads();

    // per-thread staging slots: 5 elements, fixed (m, k) per thread
    int s_m[5], s_base[5], s_c[5];
    #pragma unroll
    for (int k2 = 0; k2 < 5; k2++) {
        int e = tid + k2 * 512;
        int m = e / 40, kp = e % 40;
        int k = kp * 2;
        int ks = k >> 4, kk = k & 15;
        int mt = m >> 4;
        int reg = ((kk >> 3) << 1) | ((m >> 3) & 1);
        int ln  = ((m & 7) << 2) | ((kk >> 1) & 3);
        s_m[k2] = m;
        s_c[k2] = k;
        s_base[k2] = ((ks * 4 + mt) * 32 + ln) * 4 + reg;
    }

    int tile = blockIdx.x;
    float2 pf[5];
    if (tile < NTILES) {
        int rowbase = tile * 64;
        #pragma unroll
        for (int k2 = 0; k2 < 5; k2++) {
            int grow = rowbase + s_m[k2];
            int c = s_c[k2];
            pf[k2] = (c < 16)
                ? *(const float2*)&g_watch[grow * 16 + c]
                : *(const float2*)&g_sus[(size_t)grow * 64 + (c - 16)];
        }
    }

    for (; tile < NTILES; tile += gridDim.x) {
        int rowbase = tile * 64;

        // ---- convert prefetched A rows into fp16 fragments (single plane) ----
        #pragma unroll
        for (int k2 = 0; k2 < 5; k2++) {
            sAh[s_base[k2]] = pack_h2(pf[k2].x, pf[k2].y);
        }

        // ---- prefetch next tile's A rows (consumed next iteration) ----
        int nxt = tile + gridDim.x;
        if (nxt < NTILES) {
            int rb2 = nxt * 64;
            #pragma unroll
            for (int k2 = 0; k2 < 5; k2++) {
                int grow = rb2 + s_m[k2];
                int c = s_c[k2];
                pf[k2] = (c < 16)
                    ? *(const float2*)&g_watch[grow * 16 + c]
                    : *(const float2*)&g_sus[(size_t)grow * 64 + (c - 16)];
            }
        }
        __syncthreads();

        // ---- mma main loop: SINGLE pass (fp16 A x fp16 B) ----
        float acc[2][8][4];
        #pragma unroll
        for (int nt = 0; nt < 8; nt++) {
            float2 b2 = *(const float2*)&sBd[nw * 64 + nt * 8 + tig * 2];
            #pragma unroll
            for (int mt = 0; mt < 2; mt++) {
                acc[mt][nt][0] = b2.x; acc[mt][nt][1] = b2.y;
                acc[mt][nt][2] = b2.x; acc[mt][nt][3] = b2.y;
            }
        }
        #pragma unroll
        for (int ks = 0; ks < 5; ks++) {
            uint4 aH0 = ((const uint4*)sAh)[(ks * 4 + mw * 2 + 0) * 32 + lane];
            uint4 aH1 = ((const uint4*)sAh)[(ks * 4 + mw * 2 + 1) * 32 + lane];
            #pragma unroll
            for (int nt = 0; nt < 8; nt++) {
                uint2 b = sB[(ks * 64 + nw * 8 + nt) * 32 + lane];
                mma16816h(acc[0][nt], aH0.x, aH0.y, aH0.z, aH0.w, b.x, b.y);
                mma16816h(acc[1][nt], aH1.x, aH1.y, aH1.z, aH1.w, b.x, b.y);
            }
        }

        // ---- epilogue: per-row LN over 512 cols ----
        float s1v[2][2], s2v[2][2];
        #pragma unroll
        for (int mt = 0; mt < 2; mt++)
            #pragma unroll
            for (int rh = 0; rh < 2; rh++) {
                float s1 = 0.f, s2 = 0.f;
                #pragma unroll
                for (int nt = 0; nt < 8; nt++) {
                    float x = acc[mt][nt][rh * 2], y = acc[mt][nt][rh * 2 + 1];
                    s1 += x + y;
                    s2 = fmaf(x, x, s2); s2 = fmaf(y, y, s2);
                }
                s1 += __shfl_xor_sync(0xffffffffu, s1, 1);
                s2 += __shfl_xor_sync(0xffffffffu, s2, 1);
                s1 += __shfl_xor_sync(0xffffffffu, s1, 2);
                s2 += __shfl_xor_sync(0xffffffffu, s2, 2);
                s1v[mt][rh] = s1; s2v[mt][rh] = s2;
            }
        if (tig == 0) {
            #pragma unroll
            for (int mt = 0; mt < 2; mt++)
                #pragma unroll
                for (int rh = 0; rh < 2; rh++) {
                    int m = mw * 32 + mt * 16 + rh * 8 + g;
                    sRed[m * 8 + nw] = make_float2(s1v[mt][rh], s2v[mt][rh]);
                }
        }
        __syncthreads();

        #pragma unroll
        for (int mt = 0; mt < 2; mt++)
            #pragma unroll
            for (int rh = 0; rh < 2; rh++) {
                int m = mw * 32 + mt * 16 + rh * 8 + g;
                float t1 = 0.f, t2 = 0.f;
                #pragma unroll
                for (int w8 = 0; w8 < 8; w8++) {
                    float2 pr = sRed[m * 8 + w8];
                    t1 += pr.x; t2 += pr.y;
                }
                float mean = t1 * (1.0f / 512.0f);
                float var  = fmaxf(t2 * (1.0f / 512.0f) - mean * mean, 0.0f);
                float inv  = rsqrtf(var + 1e-5f);
                size_t grow = (size_t)(rowbase + m);
                #pragma unroll
                for (int nt = 0; nt < 8; nt++) {
                    int cidx = nw * 64 + nt * 8 + tig * 2;
                    float2 gg = *(const float2*)&sG[cidx];
                    float2 bb = *(const float2*)&sBc[cidx];
                    float x = acc[mt][nt][rh * 2], y = acc[mt][nt][rh * 2 + 1];
                    float2 o;
                    o.x = (x - mean) * inv * gg.x + bb.x;
                    o.y = (y - mean) * inv * gg.y + bb.y;
                    *(float2*)&out[grow * 512 + cidx] = o;
                }
            }
        __syncthreads();   // protect sRed/sA before next tile's stage writes
    }
}

// ---------------- launcher ----------------------------------------------------
extern "C" void kernel_launch(void* const* d_in, const int* in_sizes, int n_in,
                              void* d_out, int out_size) {
    const void*  x     = d_in[0];
    const float* emb   = (const float*)d_in[1];
    const float* Wq    = (const float*)d_in[2];
    const float* bq    = (const float*)d_in[3];
    const float* Wk    = (const float*)d_in[4];
    const float* bk    = (const float*)d_in[5];
    const float* Wv    = (const float*)d_in[6];
    const float* bv    = (const float*)d_in[7];
    const float* glim  = (const float*)d_in[8];
    const float* blim  = (const float*)d_in[9];
    const float* Ws    = (const float*)d_in[10];
    const float* bs    = (const float*)d_in[11];
    const float* gdb   = (const float*)d_in[12];
    const float* bdb   = (const float*)d_in[13];
    const float* Wd    = (const float*)d_in[14];
    const float* bd    = (const float*)d_in[15];
    const float* gch   = (const float*)d_in[16];
    const float* bch   = (const float*)d_in[17];
    float* out = (float*)d_out;

    cudaFuncSetAttribute(k_phaseC, cudaFuncAttributeMaxDynamicSharedMemorySize,
                         C_SMEM_BYTES);

    k_detect<<<1, 32>>>((const unsigned int*)x);
    k_prepB<<<40, 256>>>(Wd);
    k_phaseA<<<BSZ * NCHK, 256>>>(x, emb, Wq, bq, Wk, bk, Wv, bv,
                                  glim, blim, Ws, bs);
    k_phaseB<<<BSZ * 16 / 8, 128>>>(Ws, gdb, bdb);
    k_phaseC<<<152, 512, C_SMEM_BYTES>>>(bd, gch, bch, out);
}

// round 16
// speedup vs baseline: 1.1619x; 1.1619x over previous
#include <cuda_runtime.h>
#include <cuda_fp16.h>
#include <math.h>

#define NCHK 256
#define BSZ 32
#define NROWS (BSZ * NCHK * 16)   // 131072 rows of the flattened GEMM
#define NTILES (NROWS / 64)

// ---------------- scratch (static device globals; no allocation) -------------
__device__ int   g_is64;
__device__ float g_watch[NROWS * 16];  // [row][16]
__device__ float g_A[NROWS * 64];      // [(b*16+r)*NCHK + t][64]
__device__ float g_sus[NROWS * 64];    // [row][64]
__device__ uint2 g_Bfrag2[5 * 64 * 32]; // Wd fp16 fragments

// ---------------- packed f32x2 / misc helpers ---------------------------------
__device__ __forceinline__ unsigned long long pk2(float lo, float hi) {
    unsigned long long r;
    asm("mov.b64 %0, {%1,%2};" : "=l"(r) : "f"(lo), "f"(hi));
    return r;
}
__device__ __forceinline__ void upk2(unsigned long long v, float& lo, float& hi) {
    asm("mov.b64 {%0,%1}, %2;" : "=f"(lo), "=f"(hi) : "l"(v));
}
__device__ __forceinline__ unsigned long long fma2(unsigned long long a,
                                                   unsigned long long b,
                                                   unsigned long long c) {
    unsigned long long d;
    asm("fma.rn.f32x2 %0, %1, %2, %3;" : "=l"(d) : "l"(a), "l"(b), "l"(c));
    return d;
}

__device__ __forceinline__ unsigned pack_h2(float a, float b) {
    __half ha = __float2half_rn(a), hb = __float2half_rn(b);
    return (unsigned)__half_as_ushort(ha) | ((unsigned)__half_as_ushort(hb) << 16);
}

__device__ __forceinline__ void mma16816h(float* d,
                                          unsigned a0, unsigned a1, unsigned a2, unsigned a3,
                                          unsigned b0, unsigned b1) {
    asm volatile(
        "mma.sync.aligned.m16n8k16.row.col.f32.f16.f16.f32 "
        "{%0,%1,%2,%3}, {%4,%5,%6,%7}, {%8,%9}, {%0,%1,%2,%3};"
        : "+f"(d[0]), "+f"(d[1]), "+f"(d[2]), "+f"(d[3])
        : "r"(a0), "r"(a1), "r"(a2), "r"(a3), "r"(b0), "r"(b1));
}

// ---------------- kernel: Wd fp16 fragments + dtype detect (merged) ----------
__global__ void k_prep(const float* __restrict__ Wd,
                       const unsigned int* __restrict__ x) {
    if (blockIdx.x == 0 && threadIdx.x < 32) {
        unsigned int v = x[threadIdx.x * 2 + 1];
        unsigned int any = __ballot_sync(0xffffffffu, v != 0u);
        if (threadIdx.x == 0) g_is64 = (any == 0u) ? 1 : 0;
    }
    int w = blockIdx.x * blockDim.x + threadIdx.x;   // 0..10239
    if (w >= 5 * 64 * 32) return;
    int lane = w & 31;
    int ntg  = (w >> 5) & 63;
    int ks   = w >> 11;
    int g = lane >> 2, tig = lane & 3;
    int n  = ntg * 8 + g;
    int k0 = ks * 16 + tig * 2;
    float w00 = Wd[k0 * 512 + n],       w01 = Wd[(k0 + 1) * 512 + n];
    float w10 = Wd[(k0 + 8) * 512 + n], w11 = Wd[(k0 + 9) * 512 + n];
    g_Bfrag2[w] = make_uint2(pack_h2(w00, w01), pack_h2(w10, w11));
}

// ---------------- Phase A: attention + LN + A = watch@Ws_top + bs ------------
// Row-local arrays (rd/ps/wls) are produced & consumed by the same half-warp,
// so two block barriers are demoted to __syncwarp.
__global__ __launch_bounds__(256) void k_phaseA(
    const void* __restrict__ xraw, const float* __restrict__ emb,
    const float* __restrict__ Wq, const float* __restrict__ bq,
    const float* __restrict__ Wk, const float* __restrict__ bk,
    const float* __restrict__ Wv, const float* __restrict__ bv,
    const float* __restrict__ glim, const float* __restrict__ blim,
    const float* __restrict__ Ws, const float* __restrict__ bs)
{
    int bt = blockIdx.x;
    int tid = threadIdx.x;
    int i = tid >> 4, j = tid & 15;

    __shared__ float rd[16][17], qs[16][17], ks[16][17], vs[16][17];
    __shared__ float ps[16][17], wls[16][17];
    __shared__ float wq_s[256], wk_s[256], wv_s[256];
    __shared__ float ws_s[16 * 64];   // Ws rows 0..15 (the watch part)

    wq_s[tid] = Wq[tid];
    wk_s[tid] = Wk[tid];
    wv_s[tid] = Wv[tid];
    #pragma unroll
    for (int k = 0; k < 4; k++) ws_s[tid + k * 256] = Ws[tid + k * 256];

    long long id;
    int xbase = bt * 16 + i;
    if (g_is64) id = ((const long long*)xraw)[xbase];
    else        id = (long long)((const int*)xraw)[xbase];
    rd[i][j] = emb[(int)id * 16 + j];
    __syncthreads();                      // covers weights + rd

    float aq = bq[j], ak = bk[j], av = bv[j];
    #pragma unroll
    for (int d = 0; d < 16; d++) {
        float r = rd[i][d];
        aq = fmaf(r, wq_s[d * 16 + j], aq);
        ak = fmaf(r, wk_s[d * 16 + j], ak);
        av = fmaf(r, wv_s[d * 16 + j], av);
    }
    qs[i][j] = aq; ks[i][j] = ak; vs[i][j] = av;
    __syncthreads();                      // q/k/v cross-row

    float sc = 0.f;
    #pragma unroll
    for (int d = 0; d < 16; d++) sc = fmaf(qs[i][d], ks[j][d], sc);
    sc *= 0.25f;

    float mx = sc;
    #pragma unroll
    for (int o = 8; o; o >>= 1) mx = fmaxf(mx, __shfl_xor_sync(0xffffffffu, mx, o));
    float e = __expf(sc - mx);
    float sm = e;
    #pragma unroll
    for (int o = 8; o; o >>= 1) sm += __shfl_xor_sync(0xffffffffu, sm, o);
    float p = e / sm;
    ps[i][j] = p;
    __syncwarp();                         // ps row-local (half-warp)

    float w = 0.f;
    #pragma unroll
    for (int d = 0; d < 16; d++) w = fmaf(ps[i][d], vs[d][j], w);

    float s1 = w, s2 = w * w;
    #pragma unroll
    for (int o = 8; o; o >>= 1) {
        s1 += __shfl_xor_sync(0xffffffffu, s1, o);
        s2 += __shfl_xor_sync(0xffffffffu, s2, o);
    }
    float mean = s1 * 0.0625f;
    float var = fmaxf(s2 * 0.0625f - mean * mean, 0.0f);
    float wl = (w - mean) * rsqrtf(var + 1e-5f) * glim[j] + blim[j];

    g_watch[(bt * 16 + i) * 16 + j] = wl;
    wls[i][j] = wl;
    __syncwarp();                         // wls row-local (half-warp)

    int b = bt >> 8, t = bt & 255;
    int abase = ((b * 16 + i) * NCHK + t) * 64;
    #pragma unroll
    for (int cc = 0; cc < 4; cc++) {
        int c = j + cc * 16;
        float a = bs[c];
        #pragma unroll
        for (int d = 0; d < 16; d++) a = fmaf(wls[i][d], ws_s[d * 64 + c], a);
        g_A[abase + c] = a;
    }
}

// ---------------- Phase B: 512 chains, 4 per block (one per warp) ------------
// R7/R13 structure — measured optimum across 6 variants. Do not touch.
__global__ __launch_bounds__(128) void k_phaseB(
    const float* __restrict__ Ws,
    const float* __restrict__ gdb, const float* __restrict__ bdb)
{
    int wid = threadIdx.x >> 5;
    int lane = threadIdx.x & 31;
    int br = blockIdx.x * 4 + wid;       // chain index 0..511
    int j0 = lane, j1 = lane + 32;

    __shared__ __align__(16) float2 gsh[4][2][32];   // per-warp g buffers
    __shared__ float gdsh[64], bdsh[64];

    if (threadIdx.x < 64) {
        gdsh[threadIdx.x] = gdb[threadIdx.x];
        bdsh[threadIdx.x] = bdb[threadIdx.x];
    }
    __syncthreads();

    unsigned long long w2a[32], w2b[32];
    float q0 = 0.f, q1 = 0.f, c0 = 0.f, c1 = 0.f;
    #pragma unroll
    for (int i = 0; i < 32; i++) {
        float wa0 = Ws[(16 + i) * 64 + j0];
        float wb0 = Ws[(16 + i + 32) * 64 + j0];
        float wa1 = Ws[(16 + i) * 64 + j1];
        float wb1 = Ws[(16 + i + 32) * 64 + j1];
        float gi = gdsh[i], gi32 = gdsh[i + 32];
        float va0 = wa0 * gi, vb0 = wb0 * gi32;
        float va1 = wa1 * gi, vb1 = wb1 * gi32;
        w2a[i] = pk2(va0, vb0);
        w2b[i] = pk2(va1, vb1);
        q0 += va0 + vb0; q1 += va1 + vb1;
        c0 = fmaf(bdsh[i], wa0, c0); c0 = fmaf(bdsh[i + 32], wb0, c0);
        c1 = fmaf(bdsh[i], wa1, c1); c1 = fmaf(bdsh[i + 32], wb1, c1);
    }
    float gd0 = gdsh[j0], gd1 = gdsh[j1];
    float bd0 = bdsh[j0], bd1 = bdsh[j1];

    const float* Arow = g_A + (size_t)br * (NCHK * 64);
    float* susp = g_sus + (size_t)(br >> 4) * (NCHK * 16 * 64) + (size_t)(br & 15) * 64;

    float pa[4], pb[4];
    #pragma unroll
    for (int d = 0; d < 4; d++) {
        pa[d] = Arow[d * 64 + j0];
        pb[d] = Arow[d * 64 + j1];
    }

    float g0 = 0.f, g1 = 0.f, mean = 0.f, inv = 0.f, p0 = 0.f, p1 = 0.f;

    for (int tt = 0; tt < NCHK; tt += 4) {
        #pragma unroll
        for (int d = 0; d < 4; d++) {
            int t = tt + d;
            float s0 = (t == 0) ? 0.f : (g0 - mean) * inv * gd0 + bd0;
            float s1 = (t == 0) ? 0.f : (g1 - mean) * inv * gd1 + bd1;
            susp[(size_t)t * 1024 + j0] = s0;
            susp[(size_t)t * 1024 + j1] = s1;
            if (t == NCHK - 1) break;

            float nim = -(inv * mean);
            float h0 = (t == 0) ? pa[0] : fmaf(inv, p0, fmaf(nim, q0, pa[d] + c0));
            float h1 = (t == 0) ? pb[0] : fmaf(inv, p1, fmaf(nim, q1, pb[d] + c1));

            if (t + 4 < NCHK) {
                pa[d] = Arow[(t + 4) * 64 + j0];
                pb[d] = Arow[(t + 4) * 64 + j1];
            }

            g0 = 0.5f * h0 * (1.0f + erff(h0 * 0.70710678118654752f));
            g1 = 0.5f * h1 * (1.0f + erff(h1 * 0.70710678118654752f));

            int pbuf = t & 1;
            gsh[wid][pbuf][lane] = make_float2(g0, g1);

            float r1 = g0 + g1;
            float r2 = fmaf(g0, g0, g1 * g1);
            #pragma unroll
            for (int o = 16; o; o >>= 1) {
                r1 += __shfl_xor_sync(0xffffffffu, r1, o);
                r2 += __shfl_xor_sync(0xffffffffu, r2, o);
            }
            __syncwarp();

            mean = r1 * (1.0f / 64.0f);
            inv = rsqrtf(fmaxf(r2 * (1.0f / 64.0f) - mean * mean, 0.0f) + 1e-5f);

            const unsigned long long* g2 = (const unsigned long long*)gsh[wid][pbuf];
            unsigned long long x0 = 0ull, x1 = 0ull, x2 = 0ull, x3 = 0ull;
            unsigned long long y0 = 0ull, y1 = 0ull, y2 = 0ull, y3 = 0ull;
            #pragma unroll
            for (int i = 0; i < 32; i += 4) {
                unsigned long long ga = g2[i],     gb = g2[i + 1];
                unsigned long long gc = g2[i + 2], gdv = g2[i + 3];
                x0 = fma2(ga,  w2a[i],     x0);  y0 = fma2(ga,  w2b[i],     y0);
                x1 = fma2(gb,  w2a[i + 1], x1);  y1 = fma2(gb,  w2b[i + 1], y1);
                x2 = fma2(gc,  w2a[i + 2], x2);  y2 = fma2(gc,  w2b[i + 2], y2);
                x3 = fma2(gdv, w2a[i + 3], x3);  y3 = fma2(gdv, w2b[i + 3], y3);
            }
            {
                float la, ha, lb, hb, lc, hc, ld, hd;
                upk2(x0, la, ha); upk2(x1, lb, hb);
                upk2(x2, lc, hc); upk2(x3, ld, hd);
                p0 = ((la + ha) + (lb + hb)) + ((lc + hc) + (ld + hd));
                upk2(y0, la, ha); upk2(y1, lb, hb);
                upk2(y2, lc, hc); upk2(y3, ld, hd);
                p1 = ((la + ha) + (lb + hb)) + ((lc + hc) + (ld + hd));
            }
        }
    }
}

// ---------------- Phase C: fp16 SINGLE-pass tensor GEMM + row LN -------------
#define C_SMEM_B    (5 * 64 * 32 * 8)    // 81920 (uint2 fragments)
#define C_SMEM_A    (5 * 4 * 32 * 16)    // 10240 (one fp16 plane)
#define C_SMEM_RED  4096
#define C_SMEM_VEC  (3 * 2048)
#define C_SMEM_BYTES (C_SMEM_B + C_SMEM_A + C_SMEM_RED + C_SMEM_VEC)

__global__ __launch_bounds__(512, 1) void k_phaseC(
    const float* __restrict__ bd, const float* __restrict__ gch,
    const float* __restrict__ bch, float* __restrict__ out)
{
    extern __shared__ char sm[];
    uint2*  sB   = (uint2*)sm;                                   // [5][64][32]
    unsigned* sAh = (unsigned*)(sm + C_SMEM_B);                  // [5][4][32][4]
    float2* sRed = (float2*)(sm + C_SMEM_B + C_SMEM_A);          // [64][8]
    float*  sG   = (float*)(sm + C_SMEM_B + C_SMEM_A + C_SMEM_RED);
    float*  sBc  = sG + 512;
    float*  sBd  = sBc + 512;

    int tid = threadIdx.x;
    int lane = tid & 31, warp = tid >> 5;
    int mw = warp & 1, nw = warp >> 1;        // 2 m-warps x 8 n-warps
    int g = lane >> 2, tig = lane & 3;

    for (int i = tid; i < 5 * 64 * 32; i += 512) sB[i] = g_Bfrag2[i];
    if (tid < 512) { sG[tid] = gch[tid]; sBc[tid] = bch[tid]; sBd[tid] = bd[tid]; }
    __syncthreads();

    // per-thread staging slots: 5 elements, fixed (m, k) per thread
    int s_m[5], s_base[5], s_c[5];
    #pragma unroll
    for (int k2 = 0; k2 < 5; k2++) {
        int e = tid + k2 * 512;
        int m = e / 40, kp = e % 40;
        int k = kp * 2;
        int ks = k >> 4, kk = k & 15;
        int mt = m >> 4;
        int reg = ((kk >> 3) << 1) | ((m >> 3) & 1);
        int ln  = ((m & 7) << 2) | ((kk >> 1) & 3);
        s_m[k2] = m;
        s_c[k2] = k;
        s_base[k2] = ((ks * 4 + mt) * 32 + ln) * 4 + reg;
    }

    int tile = blockIdx.x;
    float2 pf[5];
    if (tile < NTILES) {
        int rowbase = tile * 64;
        #pragma unroll
        for (int k2 = 0; k2 < 5; k2++) {
            int grow = rowbase + s_m[k2];
            int c = s_c[k2];
            pf[k2] = (c < 16)
                ? *(const float2*)&g_watch[grow * 16 + c]
                : *(const float2*)&g_sus[(size_t)grow * 64 + (c - 16)];
        }
    }

    for (; tile < NTILES; tile += gridDim.x) {
        int rowbase = tile * 64;

        // ---- convert prefetched A rows into fp16 fragments (single plane) ----
        #pragma unroll
        for (int k2 = 0; k2 < 5; k2++) {
            sAh[s_base[k2]] = pack_h2(pf[k2].x, pf[k2].y);
        }

        // ---- prefetch next tile's A rows (consumed next iteration) ----
        int nxt = tile + gridDim.x;
        if (nxt < NTILES) {
            int rb2 = nxt * 64;
            #pragma unroll
            for (int k2 = 0; k2 < 5; k2++) {
                int grow = rb2 + s_m[k2];
                int c = s_c[k2];
                pf[k2] = (c < 16)
                    ? *(const float2*)&g_watch[grow * 16 + c]
                    : *(const float2*)&g_sus[(size_t)grow * 64 + (c - 16)];
            }
        }
        __syncthreads();

        // ---- mma main loop: SINGLE pass (fp16 A x fp16 B) ----
        float acc[2][8][4];
        #pragma unroll
        for (int nt = 0; nt < 8; nt++) {
            float2 b2 = *(const float2*)&sBd[nw * 64 + nt * 8 + tig * 2];
            #pragma unroll
            for (int mt = 0; mt < 2; mt++) {
                acc[mt][nt][0] = b2.x; acc[mt][nt][1] = b2.y;
                acc[mt][nt][2] = b2.x; acc[mt][nt][3] = b2.y;
            }
        }
        #pragma unroll
        for (int ks = 0; ks < 5; ks++) {
            uint4 aH0 = ((const uint4*)sAh)[(ks * 4 + mw * 2 + 0) * 32 + lane];
            uint4 aH1 = ((const uint4*)sAh)[(ks * 4 + mw * 2 + 1) * 32 + lane];
            #pragma unroll
            for (int nt = 0; nt < 8; nt++) {
                uint2 b = sB[(ks * 64 + nw * 8 + nt) * 32 + lane];
                mma16816h(acc[0][nt], aH0.x, aH0.y, aH0.z, aH0.w, b.x, b.y);
                mma16816h(acc[1][nt], aH1.x, aH1.y, aH1.z, aH1.w, b.x, b.y);
            }
        }

        // ---- epilogue: per-row LN over 512 cols ----
        float s1v[2][2], s2v[2][2];
        #pragma unroll
        for (int mt = 0; mt < 2; mt++)
            #pragma unroll
            for (int rh = 0; rh < 2; rh++) {
                float s1 = 0.f, s2 = 0.f;
                #pragma unroll
                for (int nt = 0; nt < 8; nt++) {
                    float x = acc[mt][nt][rh * 2], y = acc[mt][nt][rh * 2 + 1];
                    s1 += x + y;
                    s2 = fmaf(x, x, s2); s2 = fmaf(y, y, s2);
                }
                s1 += __shfl_xor_sync(0xffffffffu, s1, 1);
                s2 += __shfl_xor_sync(0xffffffffu, s2, 1);
                s1 += __shfl_xor_sync(0xffffffffu, s1, 2);
                s2 += __shfl_xor_sync(0xffffffffu, s2, 2);
                s1v[mt][rh] = s1; s2v[mt][rh] = s2;
            }
        if (tig == 0) {
            #pragma unroll
            for (int mt = 0; mt < 2; mt++)
                #pragma unroll
                for (int rh = 0; rh < 2; rh++) {
                    int m = mw * 32 + mt * 16 + rh * 8 + g;
                    sRed[m * 8 + nw] = make_float2(s1v[mt][rh], s2v[mt][rh]);
                }
        }
        __syncthreads();

        #pragma unroll
        for (int mt = 0; mt < 2; mt++)
            #pragma unroll
            for (int rh = 0; rh < 2; rh++) {
                int m = mw * 32 + mt * 16 + rh * 8 + g;
                float t1 = 0.f, t2 = 0.f;
                #pragma unroll
                for (int w8 = 0; w8 < 8; w8++) {
                    float2 pr = sRed[m * 8 + w8];
                    t1 += pr.x; t2 += pr.y;
                }
                float mean = t1 * (1.0f / 512.0f);
                float var  = fmaxf(t2 * (1.0f / 512.0f) - mean * mean, 0.0f);
                float inv  = rsqrtf(var + 1e-5f);
                size_t grow = (size_t)(rowbase + m);
                #pragma unroll
                for (int nt = 0; nt < 8; nt++) {
                    int cidx = nw * 64 + nt * 8 + tig * 2;
                    float2 gg = *(const float2*)&sG[cidx];
                    float2 bb = *(const float2*)&sBc[cidx];
                    float x = acc[mt][nt][rh * 2], y = acc[mt][nt][rh * 2 + 1];
                    float2 o;
                    o.x = (x - mean) * inv * gg.x + bb.x;
                    o.y = (y - mean) * inv * gg.y + bb.y;
                    *(float2*)&out[grow * 512 + cidx] = o;
                }
            }
        __syncthreads();   // protect sRed/sA before next tile's stage writes
    }
}

// ---------------- launcher ----------------------------------------------------
extern "C" void kernel_launch(void* const* d_in, const int* in_sizes, int n_in,
                              void* d_out, int out_size) {
    const void*  x     = d_in[0];
    const float* emb   = (const float*)d_in[1];
    const float* Wq    = (const float*)d_in[2];
    const float* bq    = (const float*)d_in[3];
    const float* Wk    = (const float*)d_in[4];
    const float* bk    = (const float*)d_in[5];
    const float* Wv    = (const float*)d_in[6];
    const float* bv    = (const float*)d_in[7];
    const float* glim  = (const float*)d_in[8];
    const float* blim  = (const float*)d_in[9];
    const float* Ws    = (const float*)d_in[10];
    const float* bs    = (const float*)d_in[11];
    const float* gdb   = (const float*)d_in[12];
    const float* bdb   = (const float*)d_in[13];
    const float* Wd    = (const float*)d_in[14];
    const float* bd    = (const float*)d_in[15];
    const float* gch   = (const float*)d_in[16];
    const float* bch   = (const float*)d_in[17];
    float* out = (float*)d_out;

    cudaFuncSetAttribute(k_phaseC, cudaFuncAttributeMaxDynamicSharedMemorySize,
                         C_SMEM_BYTES);

    k_prep<<<40, 256>>>(Wd, (const unsigned int*)x);
    k_phaseA<<<BSZ * NCHK, 256>>>(x, emb, Wq, bq, Wk, bk, Wv, bv,
                                  glim, blim, Ws, bs);
    k_phaseB<<<BSZ * 16 / 4, 128>>>(Ws, gdb, bdb);
    k_phaseC<<<152, 512, C_SMEM_BYTES>>>(bd, gch, bch, out);
}

// round 17
// speedup vs baseline: 1.1731x; 1.0097x over previous
#include <cuda_runtime.h>
#include <cuda_fp16.h>
#include <math.h>

#define NCHK 256
#define BSZ 32
#define NROWS (BSZ * NCHK * 16)   // 131072 rows of the flattened GEMM
#define NTILES2 (NROWS / 32)      // 4096 tiles of 32 rows

// ---------------- scratch (static device globals; no allocation) -------------
__device__ int   g_is64;
__device__ float g_watch[NROWS * 16];  // [row][16]
__device__ float g_A[NROWS * 64];      // [(b*16+r)*NCHK + t][64]
__device__ float g_sus[NROWS * 64];    // [row][64]
__device__ uint2 g_Bfrag2[5 * 64 * 32]; // Wd fp16 fragments

// ---------------- packed f32x2 / misc helpers ---------------------------------
__device__ __forceinline__ unsigned long long pk2(float lo, float hi) {
    unsigned long long r;
    asm("mov.b64 %0, {%1,%2};" : "=l"(r) : "f"(lo), "f"(hi));
    return r;
}
__device__ __forceinline__ void upk2(unsigned long long v, float& lo, float& hi) {
    asm("mov.b64 {%0,%1}, %2;" : "=f"(lo), "=f"(hi) : "l"(v));
}
__device__ __forceinline__ unsigned long long fma2(unsigned long long a,
                                                   unsigned long long b,
                                                   unsigned long long c) {
    unsigned long long d;
    asm("fma.rn.f32x2 %0, %1, %2, %3;" : "=l"(d) : "l"(a), "l"(b), "l"(c));
    return d;
}

__device__ __forceinline__ unsigned pack_h2(float a, float b) {
    __half ha = __float2half_rn(a), hb = __float2half_rn(b);
    return (unsigned)__half_as_ushort(ha) | ((unsigned)__half_as_ushort(hb) << 16);
}

__device__ __forceinline__ void mma16816h(float* d,
                                          unsigned a0, unsigned a1, unsigned a2, unsigned a3,
                                          unsigned b0, unsigned b1) {
    asm volatile(
        "mma.sync.aligned.m16n8k16.row.col.f32.f16.f16.f32 "
        "{%0,%1,%2,%3}, {%4,%5,%6,%7}, {%8,%9}, {%0,%1,%2,%3};"
        : "+f"(d[0]), "+f"(d[1]), "+f"(d[2]), "+f"(d[3])
        : "r"(a0), "r"(a1), "r"(a2), "r"(a3), "r"(b0), "r"(b1));
}

// ---------------- kernel: Wd fp16 fragments + dtype detect (merged) ----------
__global__ void k_prep(const float* __restrict__ Wd,
                       const unsigned int* __restrict__ x) {
    if (blockIdx.x == 0 && threadIdx.x < 32) {
        unsigned int v = x[threadIdx.x * 2 + 1];
        unsigned int any = __ballot_sync(0xffffffffu, v != 0u);
        if (threadIdx.x == 0) g_is64 = (any == 0u) ? 1 : 0;
    }
    int w = blockIdx.x * blockDim.x + threadIdx.x;   // 0..10239
    if (w >= 5 * 64 * 32) return;
    int lane = w & 31;
    int ntg  = (w >> 5) & 63;
    int ks   = w >> 11;
    int g = lane >> 2, tig = lane & 3;
    int n  = ntg * 8 + g;
    int k0 = ks * 16 + tig * 2;
    float w00 = Wd[k0 * 512 + n],       w01 = Wd[(k0 + 1) * 512 + n];
    float w10 = Wd[(k0 + 8) * 512 + n], w11 = Wd[(k0 + 9) * 512 + n];
    g_Bfrag2[w] = make_uint2(pack_h2(w00, w01), pack_h2(w10, w11));
}

// ---------------- Phase A: attention + LN + A = watch@Ws_top + bs ------------
__global__ __launch_bounds__(256) void k_phaseA(
    const void* __restrict__ xraw, const float* __restrict__ emb,
    const float* __restrict__ Wq, const float* __restrict__ bq,
    const float* __restrict__ Wk, const float* __restrict__ bk,
    const float* __restrict__ Wv, const float* __restrict__ bv,
    const float* __restrict__ glim, const float* __restrict__ blim,
    const float* __restrict__ Ws, const float* __restrict__ bs)
{
    int bt = blockIdx.x;
    int tid = threadIdx.x;
    int i = tid >> 4, j = tid & 15;

    __shared__ float rd[16][17], qs[16][17], ks[16][17], vs[16][17];
    __shared__ float ps[16][17], wls[16][17];
    __shared__ float wq_s[256], wk_s[256], wv_s[256];
    __shared__ float ws_s[16 * 64];   // Ws rows 0..15 (the watch part)

    wq_s[tid] = Wq[tid];
    wk_s[tid] = Wk[tid];
    wv_s[tid] = Wv[tid];
    #pragma unroll
    for (int k = 0; k < 4; k++) ws_s[tid + k * 256] = Ws[tid + k * 256];

    long long id;
    int xbase = bt * 16 + i;
    if (g_is64) id = ((const long long*)xraw)[xbase];
    else        id = (long long)((const int*)xraw)[xbase];
    rd[i][j] = emb[(int)id * 16 + j];
    __syncthreads();                      // covers weights + rd

    float aq = bq[j], ak = bk[j], av = bv[j];
    #pragma unroll
    for (int d = 0; d < 16; d++) {
        float r = rd[i][d];
        aq = fmaf(r, wq_s[d * 16 + j], aq);
        ak = fmaf(r, wk_s[d * 16 + j], ak);
        av = fmaf(r, wv_s[d * 16 + j], av);
    }
    qs[i][j] = aq; ks[i][j] = ak; vs[i][j] = av;
    __syncthreads();                      // q/k/v cross-row

    float sc = 0.f;
    #pragma unroll
    for (int d = 0; d < 16; d++) sc = fmaf(qs[i][d], ks[j][d], sc);
    sc *= 0.25f;

    float mx = sc;
    #pragma unroll
    for (int o = 8; o; o >>= 1) mx = fmaxf(mx, __shfl_xor_sync(0xffffffffu, mx, o));
    float e = __expf(sc - mx);
    float sm = e;
    #pragma unroll
    for (int o = 8; o; o >>= 1) sm += __shfl_xor_sync(0xffffffffu, sm, o);
    float p = e / sm;
    ps[i][j] = p;
    __syncwarp();                         // ps row-local (half-warp)

    float w = 0.f;
    #pragma unroll
    for (int d = 0; d < 16; d++) w = fmaf(ps[i][d], vs[d][j], w);

    float s1 = w, s2 = w * w;
    #pragma unroll
    for (int o = 8; o; o >>= 1) {
        s1 += __shfl_xor_sync(0xffffffffu, s1, o);
        s2 += __shfl_xor_sync(0xffffffffu, s2, o);
    }
    float mean = s1 * 0.0625f;
    float var = fmaxf(s2 * 0.0625f - mean * mean, 0.0f);
    float wl = (w - mean) * rsqrtf(var + 1e-5f) * glim[j] + blim[j];

    g_watch[(bt * 16 + i) * 16 + j] = wl;
    wls[i][j] = wl;
    __syncwarp();                         // wls row-local (half-warp)

    int b = bt >> 8, t = bt & 255;
    int abase = ((b * 16 + i) * NCHK + t) * 64;
    #pragma unroll
    for (int cc = 0; cc < 4; cc++) {
        int c = j + cc * 16;
        float a = bs[c];
        #pragma unroll
        for (int d = 0; d < 16; d++) a = fmaf(wls[i][d], ws_s[d * 64 + c], a);
        g_A[abase + c] = a;
    }
}

// ---------------- Phase B: 512 chains, 4 per block (one per warp) ------------
// R7/R13 structure — measured optimum across 6 variants. Do not touch.
__global__ __launch_bounds__(128) void k_phaseB(
    const float* __restrict__ Ws,
    const float* __restrict__ gdb, const float* __restrict__ bdb)
{
    int wid = threadIdx.x >> 5;
    int lane = threadIdx.x & 31;
    int br = blockIdx.x * 4 + wid;       // chain index 0..511
    int j0 = lane, j1 = lane + 32;

    __shared__ __align__(16) float2 gsh[4][2][32];   // per-warp g buffers
    __shared__ float gdsh[64], bdsh[64];

    if (threadIdx.x < 64) {
        gdsh[threadIdx.x] = gdb[threadIdx.x];
        bdsh[threadIdx.x] = bdb[threadIdx.x];
    }
    __syncthreads();

    unsigned long long w2a[32], w2b[32];
    float q0 = 0.f, q1 = 0.f, c0 = 0.f, c1 = 0.f;
    #pragma unroll
    for (int i = 0; i < 32; i++) {
        float wa0 = Ws[(16 + i) * 64 + j0];
        float wb0 = Ws[(16 + i + 32) * 64 + j0];
        float wa1 = Ws[(16 + i) * 64 + j1];
        float wb1 = Ws[(16 + i + 32) * 64 + j1];
        float gi = gdsh[i], gi32 = gdsh[i + 32];
        float va0 = wa0 * gi, vb0 = wb0 * gi32;
        float va1 = wa1 * gi, vb1 = wb1 * gi32;
        w2a[i] = pk2(va0, vb0);
        w2b[i] = pk2(va1, vb1);
        q0 += va0 + vb0; q1 += va1 + vb1;
        c0 = fmaf(bdsh[i], wa0, c0); c0 = fmaf(bdsh[i + 32], wb0, c0);
        c1 = fmaf(bdsh[i], wa1, c1); c1 = fmaf(bdsh[i + 32], wb1, c1);
    }
    float gd0 = gdsh[j0], gd1 = gdsh[j1];
    float bd0 = bdsh[j0], bd1 = bdsh[j1];

    const float* Arow = g_A + (size_t)br * (NCHK * 64);
    float* susp = g_sus + (size_t)(br >> 4) * (NCHK * 16 * 64) + (size_t)(br & 15) * 64;

    float pa[4], pb[4];
    #pragma unroll
    for (int d = 0; d < 4; d++) {
        pa[d] = Arow[d * 64 + j0];
        pb[d] = Arow[d * 64 + j1];
    }

    float g0 = 0.f, g1 = 0.f, mean = 0.f, inv = 0.f, p0 = 0.f, p1 = 0.f;

    for (int tt = 0; tt < NCHK; tt += 4) {
        #pragma unroll
        for (int d = 0; d < 4; d++) {
            int t = tt + d;
            float s0 = (t == 0) ? 0.f : (g0 - mean) * inv * gd0 + bd0;
            float s1 = (t == 0) ? 0.f : (g1 - mean) * inv * gd1 + bd1;
            susp[(size_t)t * 1024 + j0] = s0;
            susp[(size_t)t * 1024 + j1] = s1;
            if (t == NCHK - 1) break;

            float nim = -(inv * mean);
            float h0 = (t == 0) ? pa[0] : fmaf(inv, p0, fmaf(nim, q0, pa[d] + c0));
            float h1 = (t == 0) ? pb[0] : fmaf(inv, p1, fmaf(nim, q1, pb[d] + c1));

            if (t + 4 < NCHK) {
                pa[d] = Arow[(t + 4) * 64 + j0];
                pb[d] = Arow[(t + 4) * 64 + j1];
            }

            g0 = 0.5f * h0 * (1.0f + erff(h0 * 0.70710678118654752f));
            g1 = 0.5f * h1 * (1.0f + erff(h1 * 0.70710678118654752f));

            int pbuf = t & 1;
            gsh[wid][pbuf][lane] = make_float2(g0, g1);

            float r1 = g0 + g1;
            float r2 = fmaf(g0, g0, g1 * g1);
            #pragma unroll
            for (int o = 16; o; o >>= 1) {
                r1 += __shfl_xor_sync(0xffffffffu, r1, o);
                r2 += __shfl_xor_sync(0xffffffffu, r2, o);
            }
            __syncwarp();

            mean = r1 * (1.0f / 64.0f);
            inv = rsqrtf(fmaxf(r2 * (1.0f / 64.0f) - mean * mean, 0.0f) + 1e-5f);

            const unsigned long long* g2 = (const unsigned long long*)gsh[wid][pbuf];
            unsigned long long x0 = 0ull, x1 = 0ull, x2 = 0ull, x3 = 0ull;
            unsigned long long y0 = 0ull, y1 = 0ull, y2 = 0ull, y3 = 0ull;
            #pragma unroll
            for (int i = 0; i < 32; i += 4) {
                unsigned long long ga = g2[i],     gb = g2[i + 1];
                unsigned long long gc = g2[i + 2], gdv = g2[i + 3];
                x0 = fma2(ga,  w2a[i],     x0);  y0 = fma2(ga,  w2b[i],     y0);
                x1 = fma2(gb,  w2a[i + 1], x1);  y1 = fma2(gb,  w2b[i + 1], y1);
                x2 = fma2(gc,  w2a[i + 2], x2);  y2 = fma2(gc,  w2b[i + 2], y2);
                x3 = fma2(gdv, w2a[i + 3], x3);  y3 = fma2(gdv, w2b[i + 3], y3);
            }
            {
                float la, ha, lb, hb, lc, hc, ld, hd;
                upk2(x0, la, ha); upk2(x1, lb, hb);
                upk2(x2, lc, hc); upk2(x3, ld, hd);
                p0 = ((la + ha) + (lb + hb)) + ((lc + hc) + (ld + hd));
                upk2(y0, la, ha); upk2(y1, lb, hb);
                upk2(y2, lc, hc); upk2(y3, ld, hd);
                p1 = ((la + ha) + (lb + hb)) + ((lc + hc) + (ld + hd));
            }
        }
    }
}

// ---------------- Phase C: fp16 1-pass GEMM + row LN, M=32 tiles, 2 CTA/SM ---
#define C_SMEM_B    (5 * 64 * 32 * 8)    // 81920 (uint2 fragments)
#define C_SMEM_A    (5 * 2 * 32 * 16)    // 5120 (one fp16 plane, 2 m-tiles)
#define C_SMEM_RED  (32 * 4 * 8)         // 1024
#define C_SMEM_VEC  (3 * 2048)
#define C_SMEM_BYTES (C_SMEM_B + C_SMEM_A + C_SMEM_RED + C_SMEM_VEC)

__global__ __launch_bounds__(256, 2) void k_phaseC(
    const float* __restrict__ bd, const float* __restrict__ gch,
    const float* __restrict__ bch, float* __restrict__ out)
{
    extern __shared__ char sm[];
    uint2*  sB   = (uint2*)sm;                                   // [5][64][32]
    unsigned* sAh = (unsigned*)(sm + C_SMEM_B);                  // [5][2][32][4]
    float2* sRed = (float2*)(sm + C_SMEM_B + C_SMEM_A);          // [32][4]
    float*  sG   = (float*)(sm + C_SMEM_B + C_SMEM_A + C_SMEM_RED);
    float*  sBc  = sG + 512;
    float*  sBd  = sBc + 512;

    int tid = threadIdx.x;
    int lane = tid & 31, warp = tid >> 5;
    int mw = warp & 1, nw = warp >> 1;        // 2 m-warps x 4 n-warps
    int g = lane >> 2, tig = lane & 3;

    for (int i = tid; i < 5 * 64 * 32; i += 256) sB[i] = g_Bfrag2[i];
    for (int i = tid; i < 512; i += 256) {
        sG[i] = gch[i]; sBc[i] = bch[i]; sBd[i] = bd[i];
    }
    __syncthreads();

    // per-thread staging slots: 5 elements over 32 rows x 40 pair-cols
    int s_m[5], s_base[5], s_c[5];
    #pragma unroll
    for (int k2 = 0; k2 < 5; k2++) {
        int e = tid + k2 * 256;
        int m = e / 40, kp = e % 40;
        int k = kp * 2;
        int ks = k >> 4, kk = k & 15;
        int mt = m >> 4;
        int reg = ((kk >> 3) << 1) | ((m >> 3) & 1);
        int ln  = ((m & 7) << 2) | ((kk >> 1) & 3);
        s_m[k2] = m;
        s_c[k2] = k;
        s_base[k2] = ((ks * 2 + mt) * 32 + ln) * 4 + reg;
    }

    int tile = blockIdx.x;
    float2 pf[5];
    if (tile < NTILES2) {
        int rowbase = tile * 32;
        #pragma unroll
        for (int k2 = 0; k2 < 5; k2++) {
            int grow = rowbase + s_m[k2];
            int c = s_c[k2];
            pf[k2] = (c < 16)
                ? *(const float2*)&g_watch[grow * 16 + c]
                : *(const float2*)&g_sus[(size_t)grow * 64 + (c - 16)];
        }
    }

    for (; tile < NTILES2; tile += gridDim.x) {
        int rowbase = tile * 32;

        // ---- convert prefetched A rows into fp16 fragments ----
        #pragma unroll
        for (int k2 = 0; k2 < 5; k2++) {
            sAh[s_base[k2]] = pack_h2(pf[k2].x, pf[k2].y);
        }

        // ---- prefetch next tile's A rows ----
        int nxt = tile + gridDim.x;
        if (nxt < NTILES2) {
            int rb2 = nxt * 32;
            #pragma unroll
            for (int k2 = 0; k2 < 5; k2++) {
                int grow = rb2 + s_m[k2];
                int c = s_c[k2];
                pf[k2] = (c < 16)
                    ? *(const float2*)&g_watch[grow * 16 + c]
                    : *(const float2*)&g_sus[(size_t)grow * 64 + (c - 16)];
            }
        }
        __syncthreads();

        // ---- mma main loop: warp covers 16 rows x 128 cols ----
        float acc[16][4];
        #pragma unroll
        for (int nt = 0; nt < 16; nt++) {
            float2 b2 = *(const float2*)&sBd[nw * 128 + nt * 8 + tig * 2];
            acc[nt][0] = b2.x; acc[nt][1] = b2.y;
            acc[nt][2] = b2.x; acc[nt][3] = b2.y;
        }
        #pragma unroll
        for (int ks = 0; ks < 5; ks++) {
            uint4 aH = ((const uint4*)sAh)[(ks * 2 + mw) * 32 + lane];
            #pragma unroll
            for (int nt = 0; nt < 16; nt++) {
                uint2 b = sB[(ks * 64 + nw * 16 + nt) * 32 + lane];
                mma16816h(acc[nt], aH.x, aH.y, aH.z, aH.w, b.x, b.y);
            }
        }

        // ---- epilogue: per-row LN over 512 cols (4 n-warp partials) ----
        float s1v[2], s2v[2];
        #pragma unroll
        for (int rh = 0; rh < 2; rh++) {
            float s1 = 0.f, s2 = 0.f;
            #pragma unroll
            for (int nt = 0; nt < 16; nt++) {
                float x = acc[nt][rh * 2], y = acc[nt][rh * 2 + 1];
                s1 += x + y;
                s2 = fmaf(x, x, s2); s2 = fmaf(y, y, s2);
            }
            s1 += __shfl_xor_sync(0xffffffffu, s1, 1);
            s2 += __shfl_xor_sync(0xffffffffu, s2, 1);
            s1 += __shfl_xor_sync(0xffffffffu, s1, 2);
            s2 += __shfl_xor_sync(0xffffffffu, s2, 2);
            s1v[rh] = s1; s2v[rh] = s2;
        }
        if (tig == 0) {
            #pragma unroll
            for (int rh = 0; rh < 2; rh++) {
                int m = mw * 16 + rh * 8 + g;
                sRed[m * 4 + nw] = make_float2(s1v[rh], s2v[rh]);
            }
        }
        __syncthreads();

        #pragma unroll
        for (int rh = 0; rh < 2; rh++) {
            int m = mw * 16 + rh * 8 + g;
            float t1 = 0.f, t2 = 0.f;
            #pragma unroll
            for (int w4 = 0; w4 < 4; w4++) {
                float2 pr = sRed[m * 4 + w4];
                t1 += pr.x; t2 += pr.y;
            }
            float mean = t1 * (1.0f / 512.0f);
            float var  = fmaxf(t2 * (1.0f / 512.0f) - mean * mean, 0.0f);
            float inv  = rsqrtf(var + 1e-5f);
            size_t grow = (size_t)(rowbase + m);
            #pragma unroll
            for (int nt = 0; nt < 16; nt++) {
                int cidx = nw * 128 + nt * 8 + tig * 2;
                float2 gg = *(const float2*)&sG[cidx];
                float2 bb = *(const float2*)&sBc[cidx];
                float x = acc[nt][rh * 2], y = acc[nt][rh * 2 + 1];
                float2 o;
                o.x = (x - mean) * inv * gg.x + bb.x;
                o.y = (y - mean) * inv * gg.y + bb.y;
                *(float2*)&out[grow * 512 + cidx] = o;
            }
        }
        __syncthreads();   // protect sRed/sAh before next tile's stage writes
    }
}

// ---------------- launcher ----------------------------------------------------
extern "C" void kernel_launch(void* const* d_in, const int* in_sizes, int n_in,
                              void* d_out, int out_size) {
    const void*  x     = d_in[0];
    const float* emb   = (const float*)d_in[1];
    const float* Wq    = (const float*)d_in[2];
    const float* bq    = (const float*)d_in[3];
    const float* Wk    = (const float*)d_in[4];
    const float* bk    = (const float*)d_in[5];
    const float* Wv    = (const float*)d_in[6];
    const float* bv    = (const float*)d_in[7];
    const float* glim  = (const float*)d_in[8];
    const float* blim  = (const float*)d_in[9];
    const float* Ws    = (const float*)d_in[10];
    const float* bs    = (const float*)d_in[11];
    const float* gdb   = (const float*)d_in[12];
    const float* bdb   = (const float*)d_in[13];
    const float* Wd    = (const float*)d_in[14];
    const float* bd    = (const float*)d_in[15];
    const float* gch   = (const float*)d_in[16];
    const float* bch   = (const float*)d_in[17];
    float* out = (float*)d_out;

    cudaFuncSetAttribute(k_phaseC, cudaFuncAttributeMaxDynamicSharedMemorySize,
                         C_SMEM_BYTES);

    k_prep<<<40, 256>>>(Wd, (const unsigned int*)x);
    k_phaseA<<<BSZ * NCHK, 256>>>(x, emb, Wq, bq, Wk, bk, Wv, bv,
                                  glim, blim, Ws, bs);
    k_phaseB<<<BSZ * 16 / 4, 128>>>(Ws, gdb, bdb);
    k_phaseC<<<304, 256, C_SMEM_BYTES>>>(bd, gch, bch, out);
}